// round 15
// baseline (speedup 1.0000x reference)
#include <cuda_runtime.h>
#include <cstdint>

#define DIM 1024
#define HEADS 16
#define DH 64
#define SEQ 2048
#define NB 2
#define ROWS (NB * SEQ)        // 4096
#define SCALE 0.125f
#define LOG2E 1.4426950408889634f
#define LNEPS 1e-5f

// Global convention: "kperm" = within every 8-element k-group, element r sits at
// position p(r) = (r<4) ? 2r : 2r-7. Applied identically to both GEMM operands,
// so all mma fragment pairs (k=q4, k=q4+4) are ADJACENT -> LDS.64.

// ---------------- scratch ----------------
__device__ float g_xn[ROWS * DIM];     // layernorm out, tf32 bits, kperm along DIM
__device__ float g_q[ROWS * DIM];      // tf32, pre-scaled SCALE*LOG2E, dh kperm
__device__ float g_k[ROWS * DIM];      // tf32, dh kperm; [bh][n][dh']
__device__ float g_v[ROWS * DIM];      // tf32, TRANSPOSED [bh][dh][n]
__device__ float g_attn[ROWS * DIM];   // tf32, heads re-merged, kperm along DIM
__device__ float g_wcomb[DIM * DIM];   // (wo@w_out)^T, tf32, kperm along k
// tf32 weights: B-side transposed [n][k] kperm; wo A-side row-major kperm
__device__ float g_cwq[DIM * DIM];
__device__ float g_cwk[DIM * DIM];
__device__ float g_cwv[DIM * DIM];
__device__ float g_cwo[DIM * DIM];
__device__ float g_cwout[DIM * DIM];

// ---------------- helpers ----------------
__device__ __forceinline__ unsigned f2tf(float x) {
    unsigned u;
    asm("cvt.rna.tf32.f32 %0, %1;" : "=r"(u) : "f"(x));
    return u;
}
__device__ __forceinline__ void mma8(float* c, const unsigned* a, unsigned b0, unsigned b1) {
    asm volatile(
        "mma.sync.aligned.m16n8k8.row.col.f32.tf32.tf32.f32 "
        "{%0,%1,%2,%3}, {%4,%5,%6,%7}, {%8,%9}, {%0,%1,%2,%3};\n"
        : "+f"(c[0]), "+f"(c[1]), "+f"(c[2]), "+f"(c[3])
        : "r"(a[0]), "r"(a[1]), "r"(a[2]), "r"(a[3]), "r"(b0), "r"(b1));
}
__device__ __forceinline__ void mma8f(float* c, float a0, float a1, float a2, float a3,
                                      unsigned b0, unsigned b1) {
    asm volatile(
        "mma.sync.aligned.m16n8k8.row.col.f32.tf32.tf32.f32 "
        "{%0,%1,%2,%3}, {%4,%5,%6,%7}, {%8,%9}, {%0,%1,%2,%3};\n"
        : "+f"(c[0]), "+f"(c[1]), "+f"(c[2]), "+f"(c[3])
        : "r"(__float_as_uint(a0)), "r"(__float_as_uint(a1)),
          "r"(__float_as_uint(a2)), "r"(__float_as_uint(a3)),
          "r"(b0), "r"(b1));
}
__device__ __forceinline__ void cpa16(unsigned dst, const void* src) {
    asm volatile("cp.async.cg.shared.global [%0], [%1], 16;\n" :: "r"(dst), "l"(src));
}

// ---------------- weight conversion: tf32 + transpose + kperm ----------------
// z=0..3: {wq,wk,wv,w_out} -> transposed [n][k], kperm.  z=4: wo -> row-major, kperm cols.
__global__ void __launch_bounds__(256) cvt_w(const float* __restrict__ wq,
                                             const float* __restrict__ wk,
                                             const float* __restrict__ wv,
                                             const float* __restrict__ wo,
                                             const float* __restrict__ wout)
{
    __shared__ float ts[32][33];
    const int tx = threadIdx.x & 31, ty = threadIdx.x >> 5;   // 32 x 8
    const int bx = blockIdx.x, by = blockIdx.y, z = blockIdx.z;
    const int r = tx & 7;
    const int ptx = (tx & ~7) | ((r < 4) ? 2 * r : 2 * r - 7);

    if (z < 4) {
        const float* src = (z == 0) ? wq : (z == 1) ? wk : (z == 2) ? wv : wout;
        float* dst = (z == 0) ? g_cwq : (z == 1) ? g_cwk : (z == 2) ? g_cwv : g_cwout;
        #pragma unroll
        for (int j = 0; j < 4; j++)
            ts[ty + 8 * j][tx] = src[(size_t)(by * 32 + ty + 8 * j) * DIM + bx * 32 + tx];
        __syncthreads();
        #pragma unroll
        for (int j = 0; j < 4; j++)
            dst[(size_t)(bx * 32 + ty + 8 * j) * DIM + by * 32 + ptx] =
                __uint_as_float(f2tf(ts[tx][ty + 8 * j]));
    } else {
        #pragma unroll
        for (int j = 0; j < 4; j++) {
            float v = wo[(size_t)(by * 32 + ty + 8 * j) * DIM + bx * 32 + tx];
            g_cwo[(size_t)(by * 32 + ty + 8 * j) * DIM + bx * 32 + ptx] =
                __uint_as_float(f2tf(v));
        }
    }
}

// ---------------- LayerNorm (tf32 bits, kperm columns) ----------------
__global__ void __launch_bounds__(256) ln_kernel(const float* __restrict__ x,
                                                 const float* __restrict__ gamma,
                                                 const float* __restrict__ beta)
{
    int row = blockIdx.x;
    int t = threadIdx.x;
    const float4* xr = (const float4*)(x + (size_t)row * DIM);
    float4 v = xr[t];
    float s = v.x + v.y + v.z + v.w;
    float ss = v.x * v.x + v.y * v.y + v.z * v.z + v.w * v.w;
    #pragma unroll
    for (int o = 16; o > 0; o >>= 1) {
        s  += __shfl_xor_sync(0xffffffffu, s, o);
        ss += __shfl_xor_sync(0xffffffffu, ss, o);
    }
    __shared__ float sb[8], ssb[8];
    int w = t >> 5, ln = t & 31;
    if (ln == 0) { sb[w] = s; ssb[w] = ss; }
    __syncthreads();
    float tot = 0.f, tot2 = 0.f;
    #pragma unroll
    for (int i = 0; i < 8; i++) { tot += sb[i]; tot2 += ssb[i]; }
    float mu = tot * (1.f / DIM);
    float var = tot2 * (1.f / DIM) - mu * mu;
    float rs = rsqrtf(var + LNEPS);
    float4 g = ((const float4*)gamma)[t];
    float4 bb = ((const float4*)beta)[t];
    unsigned o0 = f2tf((v.x - mu) * rs * g.x + bb.x);
    unsigned o1 = f2tf((v.y - mu) * rs * g.y + bb.y);
    unsigned o2 = f2tf((v.z - mu) * rs * g.z + bb.z);
    unsigned o3 = f2tf((v.w - mu) * rs * g.w + bb.w);
    // cols 4t..4t+3 -> kperm positions base+off+2j
    unsigned* orow = (unsigned*)(g_xn + (size_t)row * DIM);
    int base = (4 * t) & ~7;
    int off = (t & 1);
    orow[base + off + 0] = o0;
    orow[base + off + 2] = o1;
    orow[base + off + 4] = o2;
    orow[base + off + 6] = o3;
}

// ---------------- tf32 GEMM core: 2-stage cp.async, all-LDS.64 fragments ----------------
// A [m][k] row-major kperm; B [n][k] row-major kperm (i.e. W^T). Smem pad 40
// (pair-bank = 4g+q4, conflict-free per 16-lane phase).
#define BM 128
#define BN 128
#define BK 32
#define GSTEPS (DIM / BK)       // 32
#define GPAD 40
#define AWRD (BM * GPAD)        // 5120 words
#define BWRD (BN * GPAD)        // 5120 words
#define GEMM_SMEM (2 * (AWRD + BWRD) * 4)   // 81920 bytes

__device__ __forceinline__ void gemm_issue(unsigned smbase,
                                           const float* __restrict__ A,
                                           const float* __restrict__ B,
                                           int row0, int col0, int stage, int k0)
{
    const int t = threadIdx.x;
    #pragma unroll
    for (int i = 0; i < 4; i++) {
        int id = t + 256 * i;
        int row = id >> 3, c = (id & 7) * 4;
        cpa16(smbase + (stage * AWRD + row * GPAD + c) * 4,
              A + (size_t)(row0 + row) * DIM + k0 + c);
    }
    #pragma unroll
    for (int i = 0; i < 4; i++) {
        int id = t + 256 * i;
        int row = id >> 3, c = (id & 7) * 4;
        cpa16(smbase + (2 * AWRD + stage * BWRD + row * GPAD + c) * 4,
              B + (size_t)(col0 + row) * DIM + k0 + c);
    }
    asm volatile("cp.async.commit_group;\n");
}

__device__ __forceinline__ void gemm_tc_core(const float* __restrict__ A,
                                             const float* __restrict__ B,
                                             float acc[2][8][4])
{
    extern __shared__ unsigned sm[];
    const int t = threadIdx.x;
    const int wid = t >> 5, lane = t & 31;
    const int g = lane >> 2, q4 = lane & 3;
    const int wm = wid & 3, wn = wid >> 2;
    const int row0 = blockIdx.y * BM, col0 = blockIdx.x * BN;

    unsigned smbase = (unsigned)__cvta_generic_to_shared(sm);

    gemm_issue(smbase, A, B, row0, col0, 0, 0);

    for (int s = 0; s < GSTEPS; s++) {
        asm volatile("cp.async.wait_group 0;\n");
        __syncthreads();
        if (s + 1 < GSTEPS)
            gemm_issue(smbase, A, B, row0, col0, (s + 1) & 1, (s + 1) * BK);

        const unsigned* As = sm + (s & 1) * AWRD;
        const unsigned* Bs = sm + 2 * AWRD + (s & 1) * BWRD;

        #pragma unroll
        for (int kk = 0; kk < 4; kk++) {
            unsigned af[2][4];
            #pragma unroll
            for (int mt = 0; mt < 2; mt++) {
                int r = wm * 32 + mt * 16;
                uint2 alo = *(const uint2*)&As[(r + g) * GPAD + kk * 8 + 2 * q4];
                uint2 ahi = *(const uint2*)&As[(r + g + 8) * GPAD + kk * 8 + 2 * q4];
                af[mt][0] = alo.x; af[mt][1] = ahi.x;
                af[mt][2] = alo.y; af[mt][3] = ahi.y;
            }
            #pragma unroll
            for (int nt = 0; nt < 8; nt++) {
                int cb = wn * 64 + nt * 8 + g;
                uint2 bb = *(const uint2*)&Bs[cb * GPAD + kk * 8 + 2 * q4];
                mma8(acc[0][nt], af[0], bb.x, bb.y);
                mma8(acc[1][nt], af[1], bb.x, bb.y);
            }
        }
    }
}

// ---------------- QKV projection ----------------
__global__ void __launch_bounds__(256) gemm_qkv()
{
    float acc[2][8][4] = {};
    const float* W = (blockIdx.z == 0) ? g_cwq : (blockIdx.z == 1) ? g_cwk : g_cwv;
    gemm_tc_core(g_xn, W, acc);
    const float sc = (blockIdx.z == 0) ? (SCALE * LOG2E) : 1.f;

    const int t = threadIdx.x, wid = t >> 5, lane = t & 31;
    const int g = lane >> 2, q4 = lane & 3;
    const int wm = wid & 3, wn = wid >> 2;

    if (blockIdx.z != 2) {
        float* dst = (blockIdx.z == 0) ? g_q : g_k;
        const int r0 = q4 * 2, r1 = r0 + 1;
        const int p0 = (r0 < 4) ? 2 * r0 : 2 * r0 - 7;
        const int p1 = (r1 < 4) ? 2 * r1 : 2 * r1 - 7;
        #pragma unroll
        for (int mt = 0; mt < 2; mt++) {
            #pragma unroll
            for (int nt = 0; nt < 8; nt++) {
                int cglob = blockIdx.x * BN + wn * 64 + nt * 8 + q4 * 2;
                int h = cglob >> 6;
                int dhb = (cglob & 63) & ~7;
                #pragma unroll
                for (int half = 0; half < 2; half++) {
                    int m = blockIdx.y * BM + wm * 32 + mt * 16 + g + half * 8;
                    int b = m >> 11, n = m & (SEQ - 1);
                    float* rowp = dst + ((size_t)(b * HEADS + h) * SEQ + n) * DH + dhb;
                    ((unsigned*)rowp)[p0] = f2tf(acc[mt][nt][half * 2 + 0] * sc);
                    ((unsigned*)rowp)[p1] = f2tf(acc[mt][nt][half * 2 + 1] * sc);
                }
            }
        }
    } else {
        #pragma unroll
        for (int mt = 0; mt < 2; mt++) {
            #pragma unroll
            for (int nt = 0; nt < 8; nt++) {
                int cglob = blockIdx.x * BN + wn * 64 + nt * 8 + q4 * 2;
                int h = cglob >> 6;
                int dh0 = cglob & 63;
                #pragma unroll
                for (int half = 0; half < 2; half++) {
                    int m = blockIdx.y * BM + wm * 32 + mt * 16 + g + half * 8;
                    int b = m >> 11, n = m & (SEQ - 1);
                    float* base = g_v + ((size_t)(b * HEADS + h) * DH + dh0) * SEQ + n;
                    ((unsigned*)base)[0]         = f2tf(acc[mt][nt][half * 2 + 0]);
                    ((unsigned*)(base + SEQ))[0] = f2tf(acc[mt][nt][half * 2 + 1]);
                }
            }
        }
    }
}

// ---------------- wcomb = (wo @ w_out), stored TRANSPOSED [n][k] kperm ----------------
__global__ void __launch_bounds__(256) gemm_wcomb()
{
    float acc[2][8][4] = {};
    gemm_tc_core(g_cwo, g_cwout, acc);
    const int t = threadIdx.x, wid = t >> 5, lane = t & 31;
    const int g = lane >> 2, q4 = lane & 3;
    const int wm = wid & 3, wn = wid >> 2;
    const int pg = (g < 4) ? 2 * g : 2 * g - 7;   // r % 8 == g
    #pragma unroll
    for (int mt = 0; mt < 2; mt++) {
        #pragma unroll
        for (int nt = 0; nt < 8; nt++) {
            int c = blockIdx.x * BN + wn * 64 + nt * 8 + q4 * 2;
            #pragma unroll
            for (int half = 0; half < 2; half++) {
                int r = blockIdx.y * BM + wm * 32 + mt * 16 + g + half * 8;
                int rp = (r & ~7) | pg;
                ((unsigned*)g_wcomb)[(size_t)c * DIM + rp]       = f2tf(acc[mt][nt][half * 2 + 0]);
                ((unsigned*)g_wcomb)[(size_t)(c + 1) * DIM + rp] = f2tf(acc[mt][nt][half * 2 + 1]);
            }
        }
    }
}

// ---------------- final projection ----------------
__global__ void __launch_bounds__(256) gemm_out(const float* __restrict__ bias,
                                                float* __restrict__ C)
{
    float acc[2][8][4] = {};
    gemm_tc_core(g_attn, g_wcomb, acc);
    const int t = threadIdx.x, wid = t >> 5, lane = t & 31;
    const int g = lane >> 2, q4 = lane & 3;
    const int wm = wid & 3, wn = wid >> 2;
    #pragma unroll
    for (int mt = 0; mt < 2; mt++) {
        #pragma unroll
        for (int nt = 0; nt < 8; nt++) {
            int c = blockIdx.x * BN + wn * 64 + nt * 8 + q4 * 2;
            float2 bb = *(const float2*)(bias + c);
            #pragma unroll
            for (int half = 0; half < 2; half++) {
                int r = blockIdx.y * BM + wm * 32 + mt * 16 + g + half * 8;
                float2 o = make_float2(acc[mt][nt][half * 2 + 0] + bb.x,
                                       acc[mt][nt][half * 2 + 1] + bb.y);
                *(float2*)(C + (size_t)r * DIM + c) = o;
            }
        }
    }
}

// ---------------- tf32 flash attention (R13 winner; epilogue writes kperm) ----------------
#define KPAD 72
#define VPAD 72
#define KW (64 * KPAD)
#define VW (64 * VPAD)
#define NT (SEQ / 64)
#define ATTN_SMEM ((3 * KW + 3 * VW) * 4)   // 110592 bytes

__global__ void __launch_bounds__(256) attn_tc()
{
    extern __shared__ unsigned dsm[];

    const int t = threadIdx.x, wid = t >> 5, lane = t & 31;
    const int g = lane >> 2, q4 = lane & 3;
    const int bh = blockIdx.y;
    const int q0 = blockIdx.x * 128 + wid * 16;

    const float* qb = g_q + (size_t)bh * SEQ * DH;
    const float* kb = g_k + (size_t)bh * SEQ * DH;
    const float* vb = g_v + (size_t)bh * DH * SEQ;

    const int lr = t >> 2, lc = (t & 3) * 4;
    unsigned kst[3], vst[3];
    kst[0] = (unsigned)__cvta_generic_to_shared(dsm + lr * KPAD + lc);
    kst[1] = kst[0] + KW * 4;
    kst[2] = kst[0] + 2 * KW * 4;
    vst[0] = (unsigned)__cvta_generic_to_shared(dsm + 3 * KW + lr * VPAD + lc);
    vst[1] = vst[0] + VW * 4;
    vst[2] = vst[0] + 2 * VW * 4;
    const float* kgp = kb + (size_t)lr * DH + lc;
    const float* vgp = vb + (size_t)lr * SEQ + lc;

    #pragma unroll
    for (int i = 0; i < 4; i++) cpa16(kst[0] + i * 64, kgp + 16 * i);
    #pragma unroll
    for (int i = 0; i < 4; i++) cpa16(vst[0] + i * 64, vgp + 16 * i);
    asm volatile("cp.async.commit_group;\n");
    #pragma unroll
    for (int i = 0; i < 4; i++) cpa16(kst[1] + i * 64, kgp + 64 * DH + 16 * i);
    #pragma unroll
    for (int i = 0; i < 4; i++) cpa16(vst[1] + i * 64, vgp + 64 + 16 * i);
    asm volatile("cp.async.commit_group;\n");

    unsigned qf[8][4];
    {
        const float* qr0 = qb + (size_t)(q0 + g) * DH;
        const float* qr1 = qb + (size_t)(q0 + g + 8) * DH;
        #pragma unroll
        for (int kk = 0; kk < 8; kk++) {
            uint2 a = *(const uint2*)(qr0 + kk * 8 + 2 * q4);
            uint2 b = *(const uint2*)(qr1 + kk * 8 + 2 * q4);
            qf[kk][0] = a.x; qf[kk][2] = a.y;
            qf[kk][1] = b.x; qf[kk][3] = b.y;
        }
    }

    float o[8][4];
    #pragma unroll
    for (int nt = 0; nt < 8; nt++)
        #pragma unroll
        for (int j = 0; j < 4; j++) o[nt][j] = 0.f;
    float lA = 0.f, lB = 0.f;

    for (int kt = 0; kt < NT; kt++) {
        if (kt < NT - 1) asm volatile("cp.async.wait_group 1;\n");
        else             asm volatile("cp.async.wait_group 0;\n");
        __syncthreads();

        if (kt + 2 < NT) {
            int nb = (kt + 2) % 3;
            const float* kn = kgp + (size_t)(kt + 2) * 64 * DH;
            const float* vn = vgp + (size_t)(kt + 2) * 64;
            #pragma unroll
            for (int i = 0; i < 4; i++) cpa16(kst[nb] + i * 64, kn + 16 * i);
            #pragma unroll
            for (int i = 0; i < 4; i++) cpa16(vst[nb] + i * 64, vn + 16 * i);
            asm volatile("cp.async.commit_group;\n");
        }

        const unsigned* Ks = dsm + (size_t)(kt % 3) * KW;
        const unsigned* Vs = dsm + 3 * KW + (size_t)(kt % 3) * VW;

        float s[8][4];
        #pragma unroll
        for (int nt = 0; nt < 8; nt++)
            #pragma unroll
            for (int j = 0; j < 4; j++) s[nt][j] = 0.f;
        #pragma unroll
        for (int kk = 0; kk < 8; kk++) {
            #pragma unroll
            for (int nt = 0; nt < 8; nt++) {
                uint2 bb = *(const uint2*)&Ks[(nt * 8 + g) * KPAD + kk * 8 + 2 * q4];
                mma8(s[nt], qf[kk], bb.x, bb.y);
            }
        }

        #pragma unroll
        for (int nt = 0; nt < 8; nt++) {
            #pragma unroll
            for (int j = 0; j < 4; j++)
                s[nt][j] = __uint_as_float(f2tf(exp2f(s[nt][j])));
            lA += s[nt][0] + s[nt][1];
            lB += s[nt][2] + s[nt][3];
        }

        #pragma unroll
        for (int kk = 0; kk < 8; kk++) {
            #pragma unroll
            for (int nt = 0; nt < 8; nt++) {
                uint2 bb = *(const uint2*)&Vs[(nt * 8 + g) * VPAD + kk * 8 + 2 * q4];
                mma8f(o[nt], s[kk][0], s[kk][2], s[kk][1], s[kk][3], bb.x, bb.y);
            }
        }
    }

    lA += __shfl_xor_sync(0xffffffffu, lA, 1);
    lA += __shfl_xor_sync(0xffffffffu, lA, 2);
    lB += __shfl_xor_sync(0xffffffffu, lB, 1);
    lB += __shfl_xor_sync(0xffffffffu, lB, 2);
    float iA = 1.f / lA, iB = 1.f / lB;
    int b = bh >> 4, h = bh & 15;
    int nA = blockIdx.x * 128 + wid * 16 + g;
    // kperm positions for cols 2q4 and 2q4+1 of each 8-group
    const int pa = (q4 < 2) ? 4 * q4 : 4 * q4 - 7;
    const int pb = (q4 < 2) ? 4 * q4 + 2 : 4 * q4 - 5;
    unsigned* rowA = (unsigned*)(g_attn + ((size_t)b * SEQ + nA) * DIM + h * 64);
    unsigned* rowB = (unsigned*)(g_attn + ((size_t)b * SEQ + nA + 8) * DIM + h * 64);
    #pragma unroll
    for (int nt = 0; nt < 8; nt++) {
        rowA[nt * 8 + pa] = f2tf(o[nt][0] * iA);
        rowA[nt * 8 + pb] = f2tf(o[nt][1] * iA);
        rowB[nt * 8 + pa] = f2tf(o[nt][2] * iB);
        rowB[nt * 8 + pb] = f2tf(o[nt][3] * iB);
    }
}

// ---------------- launch ----------------
extern "C" void kernel_launch(void* const* d_in, const int* in_sizes, int n_in,
                              void* d_out, int out_size)
{
    const float* x     = (const float*)d_in[0];
    const float* gamma = (const float*)d_in[1];
    const float* beta  = (const float*)d_in[2];
    const float* wq    = (const float*)d_in[3];
    const float* wk    = (const float*)d_in[4];
    const float* wv    = (const float*)d_in[5];
    const float* wo    = (const float*)d_in[6];
    const float* w_out = (const float*)d_in[7];
    const float* b_out = (const float*)d_in[8];
    float* out = (float*)d_out;

    cudaFuncSetAttribute(attn_tc, cudaFuncAttributeMaxDynamicSharedMemorySize, ATTN_SMEM);
    cudaFuncSetAttribute(gemm_qkv, cudaFuncAttributeMaxDynamicSharedMemorySize, GEMM_SMEM);
    cudaFuncSetAttribute(gemm_wcomb, cudaFuncAttributeMaxDynamicSharedMemorySize, GEMM_SMEM);
    cudaFuncSetAttribute(gemm_out, cudaFuncAttributeMaxDynamicSharedMemorySize, GEMM_SMEM);

    cvt_w<<<dim3(DIM / 32, DIM / 32, 5), 256>>>(wq, wk, wv, wo, w_out);
    ln_kernel<<<ROWS, 256>>>(x, gamma, beta);
    gemm_wcomb<<<dim3(DIM / BN, DIM / BM), 256, GEMM_SMEM>>>();
    gemm_qkv<<<dim3(DIM / BN, ROWS / BM, 3), 256, GEMM_SMEM>>>();
    attn_tc<<<dim3(SEQ / 128, NB * HEADS), 256, ATTN_SMEM>>>();
    gemm_out<<<dim3(DIM / BN, ROWS / BM), 256, GEMM_SMEM>>>(b_out, out);
}

// round 16
// speedup vs baseline: 1.0233x; 1.0233x over previous
#include <cuda_runtime.h>
#include <cstdint>

#define DIM 1024
#define HEADS 16
#define DH 64
#define SEQ 2048
#define NB 2
#define ROWS (NB * SEQ)        // 4096
#define SCALE 0.125f
#define LOG2E 1.4426950408889634f
#define LNEPS 1e-5f

// ---------------- scratch ----------------
__device__ float g_xn[ROWS * DIM];     // layernorm output, tf32 bits
__device__ float g_q[ROWS * DIM];      // tf32 bits, pre-scaled SCALE*LOG2E, dh pair-permuted
__device__ float g_k[ROWS * DIM];      // tf32 bits, dh pair-permuted; [bh][n][dh']
__device__ float g_v[ROWS * DIM];      // tf32 bits, TRANSPOSED [bh][dh][n]
__device__ float g_attn[ROWS * DIM];   // tf32 bits, heads re-merged [4096,1024]
__device__ float g_wcomb[DIM * DIM];   // wo @ w_out, tf32 bits
// tf32 copies of weights
__device__ float g_cwq[DIM * DIM];
__device__ float g_cwk[DIM * DIM];
__device__ float g_cwv[DIM * DIM];
__device__ float g_cwo[DIM * DIM];
__device__ float g_cwout[DIM * DIM];

// ---------------- helpers ----------------
__device__ __forceinline__ unsigned f2tf(float x) {
    unsigned u;
    asm("cvt.rna.tf32.f32 %0, %1;" : "=r"(u) : "f"(x));
    return u;
}
__device__ __forceinline__ void mma8(float* c, const unsigned* a, unsigned b0, unsigned b1) {
    asm volatile(
        "mma.sync.aligned.m16n8k8.row.col.f32.tf32.tf32.f32 "
        "{%0,%1,%2,%3}, {%4,%5,%6,%7}, {%8,%9}, {%0,%1,%2,%3};\n"
        : "+f"(c[0]), "+f"(c[1]), "+f"(c[2]), "+f"(c[3])
        : "r"(a[0]), "r"(a[1]), "r"(a[2]), "r"(a[3]), "r"(b0), "r"(b1));
}
__device__ __forceinline__ void mma8f(float* c, float a0, float a1, float a2, float a3,
                                      unsigned b0, unsigned b1) {
    asm volatile(
        "mma.sync.aligned.m16n8k8.row.col.f32.tf32.tf32.f32 "
        "{%0,%1,%2,%3}, {%4,%5,%6,%7}, {%8,%9}, {%0,%1,%2,%3};\n"
        : "+f"(c[0]), "+f"(c[1]), "+f"(c[2]), "+f"(c[3])
        : "r"(__float_as_uint(a0)), "r"(__float_as_uint(a1)),
          "r"(__float_as_uint(a2)), "r"(__float_as_uint(a3)),
          "r"(b0), "r"(b1));
}
__device__ __forceinline__ void cpa16(unsigned dst, const void* src) {
    asm volatile("cp.async.cg.shared.global [%0], [%1], 16;\n" :: "r"(dst), "l"(src));
}

// ---------------- weight pre-conversion to tf32 ----------------
__global__ void __launch_bounds__(256) cvt_w(const float* __restrict__ wq,
                                             const float* __restrict__ wk,
                                             const float* __restrict__ wv,
                                             const float* __restrict__ wo,
                                             const float* __restrict__ wout)
{
    const float* src;
    float* dst;
    switch (blockIdx.y) {
        case 0: src = wq;   dst = g_cwq;   break;
        case 1: src = wk;   dst = g_cwk;   break;
        case 2: src = wv;   dst = g_cwv;   break;
        case 3: src = wo;   dst = g_cwo;   break;
        default: src = wout; dst = g_cwout; break;
    }
    int idx = blockIdx.x * 256 + threadIdx.x;   // float4 index
    float4 v = ((const float4*)src)[idx];
    uint4 u = make_uint4(f2tf(v.x), f2tf(v.y), f2tf(v.z), f2tf(v.w));
    ((uint4*)dst)[idx] = u;
}

// ---------------- LayerNorm (writes tf32 bits) ----------------
__global__ void __launch_bounds__(256) ln_kernel(const float* __restrict__ x,
                                                 const float* __restrict__ gamma,
                                                 const float* __restrict__ beta)
{
    int row = blockIdx.x;
    int t = threadIdx.x;
    const float4* xr = (const float4*)(x + (size_t)row * DIM);
    float4 v = xr[t];
    float s = v.x + v.y + v.z + v.w;
    float ss = v.x * v.x + v.y * v.y + v.z * v.z + v.w * v.w;
    #pragma unroll
    for (int o = 16; o > 0; o >>= 1) {
        s  += __shfl_xor_sync(0xffffffffu, s, o);
        ss += __shfl_xor_sync(0xffffffffu, ss, o);
    }
    __shared__ float sb[8], ssb[8];
    int w = t >> 5, ln = t & 31;
    if (ln == 0) { sb[w] = s; ssb[w] = ss; }
    __syncthreads();
    float tot = 0.f, tot2 = 0.f;
    #pragma unroll
    for (int i = 0; i < 8; i++) { tot += sb[i]; tot2 += ssb[i]; }
    float mu = tot * (1.f / DIM);
    float var = tot2 * (1.f / DIM) - mu * mu;
    float rs = rsqrtf(var + LNEPS);
    float4 g = ((const float4*)gamma)[t];
    float4 bb = ((const float4*)beta)[t];
    uint4 o;
    o.x = f2tf((v.x - mu) * rs * g.x + bb.x);
    o.y = f2tf((v.y - mu) * rs * g.y + bb.y);
    o.z = f2tf((v.z - mu) * rs * g.z + bb.z);
    o.w = f2tf((v.w - mu) * rs * g.w + bb.w);
    ((uint4*)(g_xn + (size_t)row * DIM))[t] = o;
}

// ---------------- tf32 GEMM core: 512 threads, 16 warps (4x4), 3-stage cp.async ----------------
// Warp tile 32x32: acc 32 regs/thread -> fits 64-reg budget -> 2 CTAs x 16 warps = 32 warps/SM.
#define BM 128
#define BN 128
#define BK 32
#define GSTEPS (DIM / BK)       // 32
#define AWRD (BM * 36)          // 4608 words per A stage (pad 36)
#define BWRD (BK * 136)         // 4352 words per B stage (pad 136)
#define GEMM_SMEM (3 * (AWRD + BWRD) * 4)   // 107520 bytes
#define GTHREADS 512

__device__ __forceinline__ void gemm_issue(unsigned smbase,
                                           const float* __restrict__ A,
                                           const float* __restrict__ B,
                                           int row0, int col0, int stage, int k0)
{
    const int t = threadIdx.x;
    #pragma unroll
    for (int i = 0; i < 2; i++) {
        int id = t + GTHREADS * i;
        int row = id >> 3, c = (id & 7) * 4;
        cpa16(smbase + (stage * AWRD + row * 36 + c) * 4,
              A + (size_t)(row0 + row) * DIM + k0 + c);
    }
    #pragma unroll
    for (int i = 0; i < 2; i++) {
        int id = t + GTHREADS * i;
        int row = id >> 5, c = (id & 31) * 4;
        cpa16(smbase + (3 * AWRD + stage * BWRD + row * 136 + c) * 4,
              B + (size_t)(k0 + row) * DIM + col0 + c);
    }
    asm volatile("cp.async.commit_group;\n");
}

__device__ __forceinline__ void gemm_tc_core(const float* __restrict__ A,
                                             const float* __restrict__ B,
                                             float acc[2][4][4])
{
    extern __shared__ unsigned sm[];
    const int t = threadIdx.x;
    const int wid = t >> 5, lane = t & 31;
    const int g = lane >> 2, q4 = lane & 3;
    const int wm = wid & 3, wn = wid >> 2;   // 4x4 warp grid
    const int row0 = blockIdx.y * BM, col0 = blockIdx.x * BN;

    unsigned smbase = (unsigned)__cvta_generic_to_shared(sm);

    gemm_issue(smbase, A, B, row0, col0, 0, 0);
    gemm_issue(smbase, A, B, row0, col0, 1, BK);

    for (int s = 0; s < GSTEPS; s++) {
        if (s < GSTEPS - 1) asm volatile("cp.async.wait_group 1;\n");
        else                asm volatile("cp.async.wait_group 0;\n");
        __syncthreads();
        if (s + 2 < GSTEPS)
            gemm_issue(smbase, A, B, row0, col0, (s + 2) % 3, (s + 2) * BK);

        const unsigned* As = sm + (s % 3) * AWRD;
        const unsigned* Bs = sm + 3 * AWRD + (s % 3) * BWRD;

        #pragma unroll
        for (int kk = 0; kk < 4; kk++) {
            unsigned af[2][4];
            #pragma unroll
            for (int mt = 0; mt < 2; mt++) {
                int r = wm * 32 + mt * 16;
                af[mt][0] = As[(r + g) * 36 + kk * 8 + q4];
                af[mt][1] = As[(r + g + 8) * 36 + kk * 8 + q4];
                af[mt][2] = As[(r + g) * 36 + kk * 8 + q4 + 4];
                af[mt][3] = As[(r + g + 8) * 36 + kk * 8 + q4 + 4];
            }
            #pragma unroll
            for (int nt = 0; nt < 4; nt++) {
                int cb = wn * 32 + nt * 8 + g;
                unsigned b0 = Bs[(kk * 8 + q4) * 136 + cb];
                unsigned b1 = Bs[(kk * 8 + q4 + 4) * 136 + cb];
                mma8(acc[0][nt], af[0], b0, b1);
                mma8(acc[1][nt], af[1], b0, b1);
            }
        }
    }
}

// ---------------- QKV projection ----------------
// q,k: dh pair-permuted within 8-groups (r -> r<4 ? 2r : 2r-7), row-major [bh][n][dh'].
// v:   transposed [bh][dh][n], natural order.
__global__ void __launch_bounds__(GTHREADS, 2) gemm_qkv()
{
    float acc[2][4][4] = {};
    const float* W = (blockIdx.z == 0) ? g_cwq : (blockIdx.z == 1) ? g_cwk : g_cwv;
    gemm_tc_core(g_xn, W, acc);
    const float sc = (blockIdx.z == 0) ? (SCALE * LOG2E) : 1.f;

    const int t = threadIdx.x, wid = t >> 5, lane = t & 31;
    const int g = lane >> 2, q4 = lane & 3;
    const int wm = wid & 3, wn = wid >> 2;

    if (blockIdx.z != 2) {
        float* dst = (blockIdx.z == 0) ? g_q : g_k;
        const int r0 = q4 * 2, r1 = r0 + 1;
        const int p0 = (r0 < 4) ? 2 * r0 : 2 * r0 - 7;
        const int p1 = (r1 < 4) ? 2 * r1 : 2 * r1 - 7;
        #pragma unroll
        for (int mt = 0; mt < 2; mt++) {
            #pragma unroll
            for (int nt = 0; nt < 4; nt++) {
                int cglob = blockIdx.x * BN + wn * 32 + nt * 8 + q4 * 2;
                int h = cglob >> 6;
                int dhb = (cglob & 63) & ~7;
                #pragma unroll
                for (int half = 0; half < 2; half++) {
                    int m = blockIdx.y * BM + wm * 32 + mt * 16 + g + half * 8;
                    int b = m >> 11, n = m & (SEQ - 1);
                    float* rowp = dst + ((size_t)(b * HEADS + h) * SEQ + n) * DH + dhb;
                    ((unsigned*)rowp)[p0] = f2tf(acc[mt][nt][half * 2 + 0] * sc);
                    ((unsigned*)rowp)[p1] = f2tf(acc[mt][nt][half * 2 + 1] * sc);
                }
            }
        }
    } else {
        #pragma unroll
        for (int mt = 0; mt < 2; mt++) {
            #pragma unroll
            for (int nt = 0; nt < 4; nt++) {
                int cglob = blockIdx.x * BN + wn * 32 + nt * 8 + q4 * 2;
                int h = cglob >> 6;
                int dh0 = cglob & 63;
                #pragma unroll
                for (int half = 0; half < 2; half++) {
                    int m = blockIdx.y * BM + wm * 32 + mt * 16 + g + half * 8;
                    int b = m >> 11, n = m & (SEQ - 1);
                    float* base = g_v + ((size_t)(b * HEADS + h) * DH + dh0) * SEQ + n;
                    ((unsigned*)base)[0]         = f2tf(acc[mt][nt][half * 2 + 0]);
                    ((unsigned*)(base + SEQ))[0] = f2tf(acc[mt][nt][half * 2 + 1]);
                }
            }
        }
    }
}

// ---------------- wcomb = wo @ w_out (tf32 out) ----------------
__global__ void __launch_bounds__(GTHREADS, 2) gemm_wcomb()
{
    float acc[2][4][4] = {};
    gemm_tc_core(g_cwo, g_cwout, acc);
    const int t = threadIdx.x, wid = t >> 5, lane = t & 31;
    const int g = lane >> 2, q4 = lane & 3;
    const int wm = wid & 3, wn = wid >> 2;
    #pragma unroll
    for (int mt = 0; mt < 2; mt++) {
        #pragma unroll
        for (int nt = 0; nt < 4; nt++) {
            int c = blockIdx.x * BN + wn * 32 + nt * 8 + q4 * 2;
            #pragma unroll
            for (int half = 0; half < 2; half++) {
                int r = blockIdx.y * BM + wm * 32 + mt * 16 + g + half * 8;
                uint2 o = make_uint2(f2tf(acc[mt][nt][half * 2 + 0]),
                                     f2tf(acc[mt][nt][half * 2 + 1]));
                *(uint2*)(g_wcomb + (size_t)r * DIM + c) = o;
            }
        }
    }
}

// ---------------- final projection ----------------
__global__ void __launch_bounds__(GTHREADS, 2) gemm_out(const float* __restrict__ bias,
                                                        float* __restrict__ C)
{
    float acc[2][4][4] = {};
    gemm_tc_core(g_attn, g_wcomb, acc);
    const int t = threadIdx.x, wid = t >> 5, lane = t & 31;
    const int g = lane >> 2, q4 = lane & 3;
    const int wm = wid & 3, wn = wid >> 2;
    #pragma unroll
    for (int mt = 0; mt < 2; mt++) {
        #pragma unroll
        for (int nt = 0; nt < 4; nt++) {
            int c = blockIdx.x * BN + wn * 32 + nt * 8 + q4 * 2;
            float2 bb = *(const float2*)(bias + c);
            #pragma unroll
            for (int half = 0; half < 2; half++) {
                int r = blockIdx.y * BM + wm * 32 + mt * 16 + g + half * 8;
                float2 o = make_float2(acc[mt][nt][half * 2 + 0] + bb.x,
                                       acc[mt][nt][half * 2 + 1] + bb.y);
                *(float2*)(C + (size_t)r * DIM + c) = o;
            }
        }
    }
}

// ---------------- tf32 flash attention (R13 winner, tf32 epilogue) ----------------
#define KPAD 72
#define VPAD 72
#define KW (64 * KPAD)
#define VW (64 * VPAD)
#define NT (SEQ / 64)
#define ATTN_SMEM ((3 * KW + 3 * VW) * 4)   // 110592 bytes

__global__ void __launch_bounds__(256) attn_tc()
{
    extern __shared__ unsigned dsm[];

    const int t = threadIdx.x, wid = t >> 5, lane = t & 31;
    const int g = lane >> 2, q4 = lane & 3;
    const int bh = blockIdx.y;
    const int q0 = blockIdx.x * 128 + wid * 16;

    const float* qb = g_q + (size_t)bh * SEQ * DH;
    const float* kb = g_k + (size_t)bh * SEQ * DH;
    const float* vb = g_v + (size_t)bh * DH * SEQ;

    const int lr = t >> 2, lc = (t & 3) * 4;
    unsigned kst[3], vst[3];
    kst[0] = (unsigned)__cvta_generic_to_shared(dsm + lr * KPAD + lc);
    kst[1] = kst[0] + KW * 4;
    kst[2] = kst[0] + 2 * KW * 4;
    vst[0] = (unsigned)__cvta_generic_to_shared(dsm + 3 * KW + lr * VPAD + lc);
    vst[1] = vst[0] + VW * 4;
    vst[2] = vst[0] + 2 * VW * 4;
    const float* kgp = kb + (size_t)lr * DH + lc;
    const float* vgp = vb + (size_t)lr * SEQ + lc;

    #pragma unroll
    for (int i = 0; i < 4; i++) cpa16(kst[0] + i * 64, kgp + 16 * i);
    #pragma unroll
    for (int i = 0; i < 4; i++) cpa16(vst[0] + i * 64, vgp + 16 * i);
    asm volatile("cp.async.commit_group;\n");
    #pragma unroll
    for (int i = 0; i < 4; i++) cpa16(kst[1] + i * 64, kgp + 64 * DH + 16 * i);
    #pragma unroll
    for (int i = 0; i < 4; i++) cpa16(vst[1] + i * 64, vgp + 64 + 16 * i);
    asm volatile("cp.async.commit_group;\n");

    unsigned qf[8][4];
    {
        const float* qr0 = qb + (size_t)(q0 + g) * DH;
        const float* qr1 = qb + (size_t)(q0 + g + 8) * DH;
        #pragma unroll
        for (int kk = 0; kk < 8; kk++) {
            uint2 a = *(const uint2*)(qr0 + kk * 8 + 2 * q4);
            uint2 b = *(const uint2*)(qr1 + kk * 8 + 2 * q4);
            qf[kk][0] = a.x; qf[kk][2] = a.y;
            qf[kk][1] = b.x; qf[kk][3] = b.y;
        }
    }

    float o[8][4];
    #pragma unroll
    for (int nt = 0; nt < 8; nt++)
        #pragma unroll
        for (int j = 0; j < 4; j++) o[nt][j] = 0.f;
    float lA = 0.f, lB = 0.f;

    for (int kt = 0; kt < NT; kt++) {
        if (kt < NT - 1) asm volatile("cp.async.wait_group 1;\n");
        else             asm volatile("cp.async.wait_group 0;\n");
        __syncthreads();

        if (kt + 2 < NT) {
            int nb = (kt + 2) % 3;
            const float* kn = kgp + (size_t)(kt + 2) * 64 * DH;
            const float* vn = vgp + (size_t)(kt + 2) * 64;
            #pragma unroll
            for (int i = 0; i < 4; i++) cpa16(kst[nb] + i * 64, kn + 16 * i);
            #pragma unroll
            for (int i = 0; i < 4; i++) cpa16(vst[nb] + i * 64, vn + 16 * i);
            asm volatile("cp.async.commit_group;\n");
        }

        const unsigned* Ks = dsm + (size_t)(kt % 3) * KW;
        const unsigned* Vs = dsm + 3 * KW + (size_t)(kt % 3) * VW;

        float s[8][4];
        #pragma unroll
        for (int nt = 0; nt < 8; nt++)
            #pragma unroll
            for (int j = 0; j < 4; j++) s[nt][j] = 0.f;
        #pragma unroll
        for (int kk = 0; kk < 8; kk++) {
            #pragma unroll
            for (int nt = 0; nt < 8; nt++) {
                uint2 bb = *(const uint2*)&Ks[(nt * 8 + g) * KPAD + kk * 8 + 2 * q4];
                mma8(s[nt], qf[kk], bb.x, bb.y);
            }
        }

        #pragma unroll
        for (int nt = 0; nt < 8; nt++) {
            #pragma unroll
            for (int j = 0; j < 4; j++)
                s[nt][j] = __uint_as_float(f2tf(exp2f(s[nt][j])));
            lA += s[nt][0] + s[nt][1];
            lB += s[nt][2] + s[nt][3];
        }

        #pragma unroll
        for (int kk = 0; kk < 8; kk++) {
            #pragma unroll
            for (int nt = 0; nt < 8; nt++) {
                uint2 bb = *(const uint2*)&Vs[(nt * 8 + g) * VPAD + kk * 8 + 2 * q4];
                mma8f(o[nt], s[kk][0], s[kk][2], s[kk][1], s[kk][3], bb.x, bb.y);
            }
        }
    }

    lA += __shfl_xor_sync(0xffffffffu, lA, 1);
    lA += __shfl_xor_sync(0xffffffffu, lA, 2);
    lB += __shfl_xor_sync(0xffffffffu, lB, 1);
    lB += __shfl_xor_sync(0xffffffffu, lB, 2);
    float iA = 1.f / lA, iB = 1.f / lB;
    int b = bh >> 4, h = bh & 15;
    int nA = blockIdx.x * 128 + wid * 16 + g;
    #pragma unroll
    for (int nt = 0; nt < 8; nt++) {
        int dh = nt * 8 + q4 * 2;
        uint2 oa = make_uint2(f2tf(o[nt][0] * iA), f2tf(o[nt][1] * iA));
        uint2 ob = make_uint2(f2tf(o[nt][2] * iB), f2tf(o[nt][3] * iB));
        *(uint2*)(g_attn + ((size_t)b * SEQ + nA) * DIM + h * 64 + dh) = oa;
        *(uint2*)(g_attn + ((size_t)b * SEQ + nA + 8) * DIM + h * 64 + dh) = ob;
    }
}

// ---------------- launch ----------------
extern "C" void kernel_launch(void* const* d_in, const int* in_sizes, int n_in,
                              void* d_out, int out_size)
{
    const float* x     = (const float*)d_in[0];
    const float* gamma = (const float*)d_in[1];
    const float* beta  = (const float*)d_in[2];
    const float* wq    = (const float*)d_in[3];
    const float* wk    = (const float*)d_in[4];
    const float* wv    = (const float*)d_in[5];
    const float* wo    = (const float*)d_in[6];
    const float* w_out = (const float*)d_in[7];
    const float* b_out = (const float*)d_in[8];
    float* out = (float*)d_out;

    cudaFuncSetAttribute(attn_tc, cudaFuncAttributeMaxDynamicSharedMemorySize, ATTN_SMEM);
    cudaFuncSetAttribute(gemm_qkv, cudaFuncAttributeMaxDynamicSharedMemorySize, GEMM_SMEM);
    cudaFuncSetAttribute(gemm_wcomb, cudaFuncAttributeMaxDynamicSharedMemorySize, GEMM_SMEM);
    cudaFuncSetAttribute(gemm_out, cudaFuncAttributeMaxDynamicSharedMemorySize, GEMM_SMEM);

    cvt_w<<<dim3(DIM * DIM / 4 / 256, 5), 256>>>(wq, wk, wv, wo, w_out);
    ln_kernel<<<ROWS, 256>>>(x, gamma, beta);
    gemm_wcomb<<<dim3(DIM / BN, DIM / BM), GTHREADS, GEMM_SMEM>>>();
    gemm_qkv<<<dim3(DIM / BN, ROWS / BM, 3), GTHREADS, GEMM_SMEM>>>();
    attn_tc<<<dim3(SEQ / 128, NB * HEADS), 256, ATTN_SMEM>>>();
    gemm_out<<<dim3(DIM / BN, ROWS / BM), GTHREADS, GEMM_SMEM>>>(b_out, out);
}